// round 10
// baseline (speedup 1.0000x reference)
#include <cuda_runtime.h>

// Problem constants (fixed shapes from reference setup_inputs)
#define IN      8192
#define OUT     8192
#define RWORDS  1024            // IN * 4 / 32 packed int32 rows
#define KSPLIT  64              // split-K factor
#define RW      (RWORDS / KSPLIT)   // 16 word-rows per block
#define TPB     256
#define OPT     4               // outputs per thread (one int4 load)
#define OBLK    (TPB * OPT)     // 1024 outputs per block
#define OTILES  (OUT / OBLK)    // 8
#define CHUNK   4               // rows per pipeline stage
#define NCHUNK  (RW / CHUNK)    // 4

// Inline-asm vector load: ptxas cannot split/sink this -> guaranteed MLP.
#define LDG4(dst, p)                                                      \
    asm volatile("ld.global.nc.v4.u32 {%0,%1,%2,%3}, [%4];"               \
                 : "=r"((dst)[0]), "=r"((dst)[1]),                        \
                   "=r"((dst)[2]), "=r"((dst)[3])                         \
                 : "l"(p))

// PRMT exponent-splice: bytes [0,0,n,0x43] -> exactly 128.0f + n (one ALU op)
__device__ __forceinline__ unsigned nib2f_bits(unsigned v, unsigned sel) {
    unsigned r;
    asm("prmt.b32 %0, %1, %2, %3;" : "=r"(r) : "r"(v), "n"(0x43000000u), "r"(sel));
    return r;
}

// Packed f32x2 FMA: accp += {lo,hi} * xp   (sm_103a FFMA2; exact fp32 math)
__device__ __forceinline__ void fma2(unsigned long long& accp,
                                     unsigned lo, unsigned hi,
                                     unsigned long long xp) {
    unsigned long long wp;
    asm("mov.b64 %0, {%1,%2};" : "=l"(wp) : "r"(lo), "r"(hi));
    asm("fma.rn.f32x2 %0, %1, %2, %3;" : "=l"(accp) : "l"(wp), "l"(xp), "l"(accp));
}

// One packed word: 8 nibbles as 4 even/odd pairs, accumulated into f32x2 pair.
// wl holds even nibbles {n0,n2,n4,n6}, wh odd {n1,n3,n5,n7} (byte b -> k=8r+2b[+1]).
__device__ __forceinline__ void proc_word2(unsigned qword, unsigned long long& accp,
                                           const unsigned long long* xp /*4 pairs*/) {
    unsigned wl = qword & 0x0F0F0F0Fu;
    unsigned wh = (qword >> 4) & 0x0F0F0F0Fu;
    fma2(accp, nib2f_bits(wl, 0x7044u), nib2f_bits(wh, 0x7044u), xp[0]);
    fma2(accp, nib2f_bits(wl, 0x7144u), nib2f_bits(wh, 0x7144u), xp[1]);
    fma2(accp, nib2f_bits(wl, 0x7244u), nib2f_bits(wh, 0x7244u), xp[2]);
    fma2(accp, nib2f_bits(wl, 0x7344u), nib2f_bits(wh, 0x7344u), xp[3]);
}

__device__ __forceinline__ float unpack_add(unsigned long long p) {
    unsigned lo, hi;
    asm("mov.b64 {%0,%1}, %2;" : "=r"(lo), "=r"(hi) : "l"(p));
    return __uint_as_float(lo) + __uint_as_float(hi);
}

__global__ void __launch_bounds__(TPB, 4)   // 4 CTAs/SM -> 64-reg cap
qmv4_kernel(const float* __restrict__ x,
            const int*   __restrict__ qw,
            const float* __restrict__ scales,
            const float* __restrict__ zeros,
            const float* __restrict__ bias,
            float* __restrict__ out)
{
    const int tid = threadIdx.x;
    const int ob  = blockIdx.x * OBLK;   // output base of this block
    const int rz  = blockIdx.y * RW;     // word-row base of this k-split

    __shared__ __align__(16) float xs[RW * 8];   // x chunk (128 floats)

    const int stride = OUT / 4;          // int4 elements per word-row
    const int4* qp = reinterpret_cast<const int4*>(qw)
                     + (size_t)rz * stride + (ob >> 2) + tid;

    // (1) Issue first-chunk weight loads FIRST — they don't depend on x.
    unsigned buf[2][CHUNK][4];
    #pragma unroll
    for (int i = 0; i < CHUNK; ++i)
        LDG4(buf[0][i], qp + (size_t)i * stride);

    // (2) Stage x while weights are in flight. Single barrier.
    if (tid < 32) {
        reinterpret_cast<float4*>(xs)[tid] =
            reinterpret_cast<const float4*>(x + rz * 8)[tid];
    }
    __syncthreads();

    unsigned long long accp0 = 0ull, accp1 = 0ull, accp2 = 0ull, accp3 = 0ull;
    const unsigned long long* xsp = reinterpret_cast<const unsigned long long*>(xs);

    #pragma unroll
    for (int c = 0; c < NCHUNK; ++c) {
        const int cur = c & 1, nxt = cur ^ 1;
        if (c + 1 < NCHUNK) {
            #pragma unroll
            for (int i = 0; i < CHUNK; ++i)
                LDG4(buf[nxt][i], qp + (size_t)(CHUNK * (c + 1) + i) * stride);
        }
        #pragma unroll
        for (int i = 0; i < CHUNK; ++i) {
            const int r = CHUNK * c + i;
            unsigned long long xp[4];    // 4 packed {x_even, x_odd} pairs of row r
            xp[0] = xsp[r * 4 + 0];
            xp[1] = xsp[r * 4 + 1];
            xp[2] = xsp[r * 4 + 2];
            xp[3] = xsp[r * 4 + 3];
            proc_word2(buf[cur][i][0], accp0, xp);
            proc_word2(buf[cur][i][1], accp1, xp);
            proc_word2(buf[cur][i][2], accp2, xp);
            proc_word2(buf[cur][i][3], accp3, xp);
        }
    }

    // (3) Per-warp xsum AFTER the loop: no barrier, no broadcast wait.
    const int lane = tid & 31;
    float4 xv = reinterpret_cast<const float4*>(xs)[lane];
    float xsum = (xv.x + xv.y) + (xv.z + xv.w);
    #pragma unroll
    for (int off = 16; off; off >>= 1)
        xsum += __shfl_xor_sync(0xffffffffu, xsum, off);

    float acc0 = unpack_add(accp0);
    float acc1 = unpack_add(accp1);
    float acc2 = unpack_add(accp2);
    float acc3 = unpack_add(accp3);

    const int o = ob + tid * OPT;
    float4 sc = *reinterpret_cast<const float4*>(scales + o);
    float4 zr = *reinterpret_cast<const float4*>(zeros  + o);

    // acc accumulated x*(128+n); subtract 128*sum(x over range) exactly.
    float r0 = sc.x * (acc0 - 128.f * xsum) - zr.x * xsum;
    float r1 = sc.y * (acc1 - 128.f * xsum) - zr.y * xsum;
    float r2 = sc.z * (acc2 - 128.f * xsum) - zr.z * xsum;
    float r3 = sc.w * (acc3 - 128.f * xsum) - zr.w * xsum;

    if (blockIdx.y == 0) {   // bias added exactly once
        float4 bi = *reinterpret_cast<const float4*>(bias + o);
        r0 += bi.x; r1 += bi.y; r2 += bi.z; r3 += bi.w;
    }

    atomicAdd(out + o + 0, r0);
    atomicAdd(out + o + 1, r1);
    atomicAdd(out + o + 2, r2);
    atomicAdd(out + o + 3, r3);
}

extern "C" void kernel_launch(void* const* d_in, const int* in_sizes, int n_in,
                              void* d_out, int out_size)
{
    const float* x      = (const float*)d_in[0];
    const int*   qw     = (const int*)  d_in[1];
    const float* scales = (const float*)d_in[2];
    const float* zeros  = (const float*)d_in[3];
    const float* bias   = (const float*)d_in[4];
    float* out = (float*)d_out;

    // Zero the split-K accumulation target every launch (graph-replay idempotent)
    cudaMemsetAsync(out, 0, OUT * sizeof(float), 0);

    dim3 grid(OTILES, KSPLIT);
    qmv4_kernel<<<grid, TPB>>>(x, qw, scales, zeros, bias, out);
}